// round 3
// baseline (speedup 1.0000x reference)
#include <cuda_runtime.h>
#include <cstddef>

// Problem constants
#define B_    4
#define C_    64
#define H_    256
#define W_    256
#define HW_   (H_*W_)          // 65536
#define WS_   8
#define OWS_  12
#define PAD_  2
#define NQ_   64
#define NO_   144
#define NH_   4
#define HEAD_ 16
#define SCALE_ 0.25f
#define NW_   1024
#define LOG2E_ 1.4426950408889634f

typedef unsigned long long ull;

// ---- packed f32x2 helpers (Blackwell) -------------------------------------
__device__ __forceinline__ ull bcast2(float v) {
    ull r; asm("mov.b64 %0, {%1,%1};" : "=l"(r) : "f"(v)); return r;
}
__device__ __forceinline__ void unpack2(ull v, float& lo, float& hi) {
    asm("mov.b64 {%0,%1}, %2;" : "=f"(lo), "=f"(hi) : "l"(v));
}
__device__ __forceinline__ ull pack2(float lo, float hi) {
    ull r; asm("mov.b64 %0, {%1,%2};" : "=l"(r) : "f"(lo), "f"(hi)); return r;
}
#define FFMA2(d, a, b) asm("fma.rn.f32x2 %0, %1, %2, %0;" : "+l"(d) : "l"(a), "l"(b))
__device__ __forceinline__ ull mul2(ull a, ull b) {
    ull r; asm("mul.rn.f32x2 %0, %1, %2;" : "=l"(r) : "l"(a), "l"(b)); return r;
}
__device__ __forceinline__ ull add2(ull a, ull b) {
    ull r; asm("add.rn.f32x2 %0, %1, %2;" : "=l"(r) : "l"(a), "l"(b)); return r;
}
__device__ __forceinline__ float ex2f(float x) {
    float r; asm("ex2.approx.f32 %0, %1;" : "=f"(r) : "f"(x)); return r;
}

// Scratch (device globals). Position-major [b][pos][c].
__device__ float g_q [(size_t)B_*HW_*C_];
__device__ float g_k [(size_t)B_*HW_*C_];
__device__ float g_v [(size_t)B_*HW_*C_];
__device__ float g_ao[(size_t)B_*HW_*C_];

// ---------------------------------------------------------------------------
// Kernel 1: QKV GEMM.  out[o,n] = sum_c W[o,c] * x[c,n] + b[o]
// Both smem operands c-contiguous so c-pairs are native f32x2 lanes.
// grid: (1024 n-tiles, 3 o-tiles, 4 batches), block 256
// ---------------------------------------------------------------------------
__global__ __launch_bounds__(256) void qkv_gemm(const float* __restrict__ x,
                                                const float* __restrict__ w,
                                                const float* __restrict__ qb)
{
    __shared__ float Ws[64][64];   // [o][c]
    __shared__ float Xs[64][68];   // [n][c], padded rows

    const int b  = blockIdx.z;
    const int ot = blockIdx.y;
    const int n0 = blockIdx.x * 64;
    const int tid = threadIdx.x;

    // W tile: rows already c-contiguous
    const float* wbase = w + (size_t)ot * 64 * 64;
    #pragma unroll
    for (int t = tid * 4; t < 4096; t += 1024) {
        *(float4*)&Ws[t >> 6][t & 63] = *(const float4*)(wbase + t);
    }
    // X tile transposed into [n][c]
    const float* xbase = x + (size_t)b * C_ * HW_ + n0;
    #pragma unroll
    for (int t = tid * 4; t < 4096; t += 1024) {
        int c = t >> 6, n = t & 63;
        float4 v4 = *(const float4*)(xbase + (size_t)c * HW_ + n);
        Xs[n+0][c] = v4.x; Xs[n+1][c] = v4.y; Xs[n+2][c] = v4.z; Xs[n+3][c] = v4.w;
    }
    __syncthreads();

    const int i = tid >> 4;
    const int j = tid & 15;

    ull acc[4][4] = {};   // c-pair partial sums (f32x2 lanes)
    #pragma unroll 8
    for (int cp = 0; cp < 16; cp++) {
        ulonglong2 wv[4], av[4];
        #pragma unroll
        for (int m = 0; m < 4; m++)
            wv[m] = *(const ulonglong2*)&Ws[i*4+m][cp*4];
        #pragma unroll
        for (int n = 0; n < 4; n++)
            av[n] = *(const ulonglong2*)&Xs[j*4+n][cp*4];
        #pragma unroll
        for (int m = 0; m < 4; m++)
            #pragma unroll
            for (int n = 0; n < 4; n++) {
                FFMA2(acc[m][n], wv[m].x, av[n].x);
                FFMA2(acc[m][n], wv[m].y, av[n].y);
            }
    }

    float vals[4][4];
    #pragma unroll
    for (int m = 0; m < 4; m++) {
        float bias = __ldg(qb + ot*64 + i*4 + m);
        #pragma unroll
        for (int n = 0; n < 4; n++) {
            float lo, hi; unpack2(acc[m][n], lo, hi);
            vals[m][n] = lo + hi + bias;
        }
    }

    float* dst = (ot == 0 ? g_q : (ot == 1 ? g_k : g_v))
               + ((size_t)b * HW_ + n0) * C_;
    #pragma unroll
    for (int n = 0; n < 4; n++) {
        float4 o4 = make_float4(vals[0][n], vals[1][n], vals[2][n], vals[3][n]);
        *(float4*)(dst + (size_t)(j*4 + n) * C_ + i*4) = o4;
    }
}

// ---------------------------------------------------------------------------
// Kernel 2: windowed overlap cross-attention, packed f32x2 math.
// One block per window, 256 threads = (head, query).
// ---------------------------------------------------------------------------
#define ATTN_SMEM ((NO_*C_*2 + NH_*361) * 4)

__global__ __launch_bounds__(256) void attn_kernel(const float* __restrict__ rpb)
{
    extern __shared__ float sm[];
    float* ks = sm;                    // [144][64]
    float* vs = sm + NO_*C_;           // [144][64]
    float* rs = sm + NO_*C_*2;         // [4][361] bias * log2e

    const int tid = threadIdx.x;
    const int b   = blockIdx.x >> 10;
    const int wi  = blockIdx.x & 1023;
    const int wh  = wi >> 5, ww = wi & 31;
    const int y0  = wh * WS_, x0 = ww * WS_;

    const float* kg = g_k + (size_t)b * HW_ * C_;
    const float* vg = g_v + (size_t)b * HW_ * C_;
    for (int t = tid; t < NO_ * (C_/4); t += 256) {
        int kk = t >> 4;
        int c4 = (t & 15) << 2;
        int gy = y0 + kk / OWS_ - PAD_;
        int gx = x0 + kk % OWS_ - PAD_;
        float4 kv = make_float4(0.f, 0.f, 0.f, 0.f);
        float4 vv = make_float4(0.f, 0.f, 0.f, 0.f);
        if ((unsigned)gy < H_ && (unsigned)gx < W_) {
            size_t off = ((size_t)gy * W_ + gx) * C_ + c4;
            kv = *(const float4*)(kg + off);
            vv = *(const float4*)(vg + off);
        }
        *(float4*)&ks[kk * C_ + c4] = kv;
        *(float4*)&vs[kk * C_ + c4] = vv;
    }
    for (int t = tid; t < 361 * NH_; t += 256) {
        int idx = t >> 2, h = t & 3;
        rs[h * 361 + idx] = __ldg(rpb + t) * LOG2E_;
    }

    const int h  = tid >> 6;
    const int qi = tid & 63;
    const int qy = qi >> 3, qx = qi & 7;

    // q registers, pre-scaled by SCALE*log2e, packed into f32x2 pairs
    const float* qg = g_q + (((size_t)b * HW_) + (size_t)(y0 + qy) * W_ + (x0 + qx)) * C_
                    + h * HEAD_;
    ull q2[8];
    const float qs = SCALE_ * LOG2E_;
    #pragma unroll
    for (int d4 = 0; d4 < 4; d4++) {
        float4 t4 = *(const float4*)(qg + d4 * 4);
        q2[d4*2+0] = pack2(t4.x * qs, t4.y * qs);
        q2[d4*2+1] = pack2(t4.z * qs, t4.w * qs);
    }
    __syncthreads();

    const float* rb = rs + h * 361 + (7 - qy) * 19 + (7 - qx);

    float l = 0.f;
    ull acc2[8] = {};

    for (int ky = 0; ky < OWS_; ky++) {
        const float* rbr = rb + ky * 19;
        #pragma unroll 6
        for (int kx = 0; kx < OWS_; kx++) {
            const int kk = ky * OWS_ + kx;
            const ulonglong2* kp = (const ulonglong2*)(ks + kk * C_ + h * HEAD_);
            ulonglong2 ka = kp[0], kb = kp[1], kc = kp[2], kd = kp[3];
            ull sa = mul2(q2[0], ka.x);
            ull sb = mul2(q2[1], ka.y);
            FFMA2(sa, q2[2], kb.x); FFMA2(sb, q2[3], kb.y);
            FFMA2(sa, q2[4], kc.x); FFMA2(sb, q2[5], kc.y);
            FFMA2(sa, q2[6], kd.x); FFMA2(sb, q2[7], kd.y);
            ull s2 = add2(sa, sb);
            float lo, hi; unpack2(s2, lo, hi);
            float p = ex2f(lo + hi + rbr[kx]);
            l += p;
            ull pp = bcast2(p);
            const ulonglong2* vp = (const ulonglong2*)(vs + kk * C_ + h * HEAD_);
            ulonglong2 va = vp[0], vb = vp[1], vc = vp[2], vd = vp[3];
            FFMA2(acc2[0], pp, va.x); FFMA2(acc2[1], pp, va.y);
            FFMA2(acc2[2], pp, vb.x); FFMA2(acc2[3], pp, vb.y);
            FFMA2(acc2[4], pp, vc.x); FFMA2(acc2[5], pp, vc.y);
            FFMA2(acc2[6], pp, vd.x); FFMA2(acc2[7], pp, vd.y);
        }
    }

    const float inv = 1.f / l;
    float* aop = g_ao + (((size_t)b * HW_) + (size_t)(y0 + qy) * W_ + (x0 + qx)) * C_
               + h * HEAD_;
    #pragma unroll
    for (int d4 = 0; d4 < 4; d4++) {
        float l0, h0, l1, h1;
        unpack2(acc2[d4*2+0], l0, h0);
        unpack2(acc2[d4*2+1], l1, h1);
        float4 o4 = make_float4(l0*inv, h0*inv, l1*inv, h1*inv);
        *(float4*)(aop + d4 * 4) = o4;
    }
}

// ---------------------------------------------------------------------------
// Kernel 3: projection GEMM.  y[b][o][n] = sum_c Wp[o,c]*ao[b][n][c] + pb[o]
// Both operands natively c-contiguous -> pure f32x2, zero packing.
// ---------------------------------------------------------------------------
__global__ __launch_bounds__(256) void proj_gemm(const float* __restrict__ w,
                                                 const float* __restrict__ pb,
                                                 float* __restrict__ out)
{
    __shared__ float Ws[64][64];   // [o][c]
    __shared__ float As[64][68];   // [n][c] padded

    const int b  = blockIdx.y;
    const int n0 = blockIdx.x * 64;
    const int tid = threadIdx.x;

    #pragma unroll
    for (int t = tid * 4; t < 4096; t += 1024) {
        *(float4*)&Ws[t >> 6][t & 63] = *(const float4*)(w + t);
    }
    const float* abase = g_ao + ((size_t)b * HW_ + n0) * C_;
    #pragma unroll
    for (int t = tid * 4; t < 4096; t += 1024) {
        int n = t >> 6, c = t & 63;
        *(float4*)&As[n][c] = *(const float4*)(abase + (size_t)n * C_ + c);
    }
    __syncthreads();

    const int i = tid >> 4;
    const int j = tid & 15;

    ull acc[4][4] = {};
    #pragma unroll 8
    for (int cp = 0; cp < 16; cp++) {
        ulonglong2 wv[4], av[4];
        #pragma unroll
        for (int m = 0; m < 4; m++)
            wv[m] = *(const ulonglong2*)&Ws[i*4+m][cp*4];
        #pragma unroll
        for (int n = 0; n < 4; n++)
            av[n] = *(const ulonglong2*)&As[j*4+n][cp*4];
        #pragma unroll
        for (int m = 0; m < 4; m++)
            #pragma unroll
            for (int n = 0; n < 4; n++) {
                FFMA2(acc[m][n], wv[m].x, av[n].x);
                FFMA2(acc[m][n], wv[m].y, av[n].y);
            }
    }

    #pragma unroll
    for (int m = 0; m < 4; m++) {
        int o = i*4 + m;
        float bias = __ldg(pb + o);
        float r[4];
        #pragma unroll
        for (int n = 0; n < 4; n++) {
            float lo, hi; unpack2(acc[m][n], lo, hi);
            r[n] = lo + hi + bias;
        }
        *(float4*)(out + ((size_t)b * C_ + o) * HW_ + n0 + j*4) =
            make_float4(r[0], r[1], r[2], r[3]);
    }
}

// ---------------------------------------------------------------------------
extern "C" void kernel_launch(void* const* d_in, const int* in_sizes, int n_in,
                              void* d_out, int out_size)
{
    const float* x      = (const float*)d_in[0];
    const float* qkv_w  = (const float*)d_in[1];
    const float* qkv_b  = (const float*)d_in[2];
    const float* rpb    = (const float*)d_in[3];
    const float* proj_w = (const float*)d_in[4];
    const float* proj_b = (const float*)d_in[5];
    float* out = (float*)d_out;

    cudaFuncSetAttribute(attn_kernel, cudaFuncAttributeMaxDynamicSharedMemorySize,
                         ATTN_SMEM);

    qkv_gemm<<<dim3(HW_/64, 3, B_), 256>>>(x, qkv_w, qkv_b);
    attn_kernel<<<B_ * NW_, 256, ATTN_SMEM>>>(rpb);
    proj_gemm<<<dim3(HW_/64, B_), 256>>>(proj_w, proj_b, out);
}

// round 4
// speedup vs baseline: 1.4037x; 1.4037x over previous
#include <cuda_runtime.h>
#include <cstddef>

// Problem constants
#define B_    4
#define C_    64
#define H_    256
#define W_    256
#define HW_   (H_*W_)          // 65536
#define WS_   8
#define OWS_  12
#define PAD_  2
#define NQ_   64
#define NO_   144
#define NH_   4
#define HEAD_ 16
#define SCALE_ 0.25f
#define NW_   1024
#define LOG2E_ 1.4426950408889634f

typedef unsigned long long ull;

// ---- packed f32x2 helpers (Blackwell) -------------------------------------
__device__ __forceinline__ ull bcast2(float v) {
    ull r; asm("mov.b64 %0, {%1,%1};" : "=l"(r) : "f"(v)); return r;
}
__device__ __forceinline__ void unpack2(ull v, float& lo, float& hi) {
    asm("mov.b64 {%0,%1}, %2;" : "=f"(lo), "=f"(hi) : "l"(v));
}
__device__ __forceinline__ ull pack2(float lo, float hi) {
    ull r; asm("mov.b64 %0, {%1,%2};" : "=l"(r) : "f"(lo), "f"(hi)); return r;
}
#define FFMA2(d, a, b) asm("fma.rn.f32x2 %0, %1, %2, %0;" : "+l"(d) : "l"(a), "l"(b))
__device__ __forceinline__ ull mul2(ull a, ull b) {
    ull r; asm("mul.rn.f32x2 %0, %1, %2;" : "=l"(r) : "l"(a), "l"(b)); return r;
}
__device__ __forceinline__ ull add2(ull a, ull b) {
    ull r; asm("add.rn.f32x2 %0, %1, %2;" : "=l"(r) : "l"(a), "l"(b)); return r;
}
__device__ __forceinline__ float ex2f(float x) {
    float r; asm("ex2.approx.f32 %0, %1;" : "=f"(r) : "f"(x)); return r;
}

// Scratch (device globals). Position-major [b][pos][c].
__device__ float g_q [(size_t)B_*HW_*C_];
__device__ float g_k [(size_t)B_*HW_*C_];
__device__ float g_v [(size_t)B_*HW_*C_];
__device__ float g_ao[(size_t)B_*HW_*C_];

// ---------------------------------------------------------------------------
// Kernel 1: QKV GEMM.  out[o,n] = sum_c W[o,c] * x[c,n] + b[o]
// R1 smem layouts (no transposes); f32x2 packed over the n dimension:
//   acc2[m][np] lanes = (n_even, n_odd), multiplier = bcast2(W[o][c]).
// grid: (1024 n-tiles, 3 o-tiles, 4 batches), block 256
// ---------------------------------------------------------------------------
__global__ __launch_bounds__(256) void qkv_gemm(const float* __restrict__ x,
                                                const float* __restrict__ w,
                                                const float* __restrict__ qb)
{
    __shared__ float Ws[64][64];  // [o][c], direct copy
    __shared__ float Xs[64][64];  // [c][n], direct copy

    const int b  = blockIdx.z;
    const int ot = blockIdx.y;
    const int n0 = blockIdx.x * 64;
    const int tid = threadIdx.x;

    const float* wbase = w + (size_t)ot * 64 * 64;
    #pragma unroll
    for (int t = tid * 4; t < 4096; t += 1024) {
        *(float4*)&Ws[t >> 6][t & 63] = *(const float4*)(wbase + t);
    }
    const float* xbase = x + (size_t)b * C_ * HW_ + n0;
    #pragma unroll
    for (int t = tid * 4; t < 4096; t += 1024) {
        int c = t >> 6, n = t & 63;
        *(float4*)&Xs[c][n] = *(const float4*)(xbase + (size_t)c * HW_ + n);
    }
    __syncthreads();

    const int i = tid >> 4;   // o micro-tile (4 rows)
    const int j = tid & 15;   // n micro-tile (4 cols = 2 f32x2 pairs)

    ull acc2[4][2] = {};
    #pragma unroll 8
    for (int c = 0; c < 64; c++) {
        float a0 = Ws[i*4+0][c];
        float a1 = Ws[i*4+1][c];
        float a2 = Ws[i*4+2][c];
        float a3 = Ws[i*4+3][c];
        ulonglong2 xv = *(const ulonglong2*)&Xs[c][j*4];
        ull w0 = bcast2(a0), w1 = bcast2(a1), w2 = bcast2(a2), w3 = bcast2(a3);
        FFMA2(acc2[0][0], w0, xv.x); FFMA2(acc2[0][1], w0, xv.y);
        FFMA2(acc2[1][0], w1, xv.x); FFMA2(acc2[1][1], w1, xv.y);
        FFMA2(acc2[2][0], w2, xv.x); FFMA2(acc2[2][1], w2, xv.y);
        FFMA2(acc2[3][0], w3, xv.x); FFMA2(acc2[3][1], w3, xv.y);
    }

    float vals[4][4];
    #pragma unroll
    for (int m = 0; m < 4; m++) {
        float bias = __ldg(qb + ot*64 + i*4 + m);
        unpack2(acc2[m][0], vals[m][0], vals[m][1]);
        unpack2(acc2[m][1], vals[m][2], vals[m][3]);
        vals[m][0] += bias; vals[m][1] += bias;
        vals[m][2] += bias; vals[m][3] += bias;
    }

    float* dst = (ot == 0 ? g_q : (ot == 1 ? g_k : g_v))
               + ((size_t)b * HW_ + n0) * C_;
    #pragma unroll
    for (int n = 0; n < 4; n++) {
        float4 o4 = make_float4(vals[0][n], vals[1][n], vals[2][n], vals[3][n]);
        *(float4*)(dst + (size_t)(j*4 + n) * C_ + i*4) = o4;
    }
}

// ---------------------------------------------------------------------------
// Kernel 2: windowed overlap cross-attention, packed f32x2 math.
// One block per window, 256 threads = (head, query). smem reads are
// warp-broadcast (all lanes same kk) -> conflict-free.
// ---------------------------------------------------------------------------
#define ATTN_SMEM ((NO_*C_*2 + NH_*361) * 4)

__global__ __launch_bounds__(256) void attn_kernel(const float* __restrict__ rpb)
{
    extern __shared__ float sm[];
    float* ks = sm;                    // [144][64]
    float* vs = sm + NO_*C_;           // [144][64]
    float* rs = sm + NO_*C_*2;         // [4][361] bias * log2e

    const int tid = threadIdx.x;
    const int b   = blockIdx.x >> 10;
    const int wi  = blockIdx.x & 1023;
    const int wh  = wi >> 5, ww = wi & 31;
    const int y0  = wh * WS_, x0 = ww * WS_;

    const float* kg = g_k + (size_t)b * HW_ * C_;
    const float* vg = g_v + (size_t)b * HW_ * C_;
    for (int t = tid; t < NO_ * (C_/4); t += 256) {
        int kk = t >> 4;
        int c4 = (t & 15) << 2;
        int gy = y0 + kk / OWS_ - PAD_;
        int gx = x0 + kk % OWS_ - PAD_;
        float4 kv = make_float4(0.f, 0.f, 0.f, 0.f);
        float4 vv = make_float4(0.f, 0.f, 0.f, 0.f);
        if ((unsigned)gy < H_ && (unsigned)gx < W_) {
            size_t off = ((size_t)gy * W_ + gx) * C_ + c4;
            kv = *(const float4*)(kg + off);
            vv = *(const float4*)(vg + off);
        }
        *(float4*)&ks[kk * C_ + c4] = kv;
        *(float4*)&vs[kk * C_ + c4] = vv;
    }
    for (int t = tid; t < 361 * NH_; t += 256) {
        int idx = t >> 2, h = t & 3;
        rs[h * 361 + idx] = __ldg(rpb + t) * LOG2E_;
    }

    const int h  = tid >> 6;
    const int qi = tid & 63;
    const int qy = qi >> 3, qx = qi & 7;

    const float* qg = g_q + (((size_t)b * HW_) + (size_t)(y0 + qy) * W_ + (x0 + qx)) * C_
                    + h * HEAD_;
    ull q2[8];
    const float qs = SCALE_ * LOG2E_;
    #pragma unroll
    for (int d4 = 0; d4 < 4; d4++) {
        float4 t4 = *(const float4*)(qg + d4 * 4);
        q2[d4*2+0] = pack2(t4.x * qs, t4.y * qs);
        q2[d4*2+1] = pack2(t4.z * qs, t4.w * qs);
    }
    __syncthreads();

    const float* rb = rs + h * 361 + (7 - qy) * 19 + (7 - qx);

    float l = 0.f;
    ull acc2[8] = {};

    for (int ky = 0; ky < OWS_; ky++) {
        const float* rbr = rb + ky * 19;
        #pragma unroll 6
        for (int kx = 0; kx < OWS_; kx++) {
            const int kk = ky * OWS_ + kx;
            const ulonglong2* kp = (const ulonglong2*)(ks + kk * C_ + h * HEAD_);
            ulonglong2 ka = kp[0], kb = kp[1], kc = kp[2], kd = kp[3];
            ull sa = mul2(q2[0], ka.x);
            ull sb = mul2(q2[1], ka.y);
            FFMA2(sa, q2[2], kb.x); FFMA2(sb, q2[3], kb.y);
            FFMA2(sa, q2[4], kc.x); FFMA2(sb, q2[5], kc.y);
            FFMA2(sa, q2[6], kd.x); FFMA2(sb, q2[7], kd.y);
            ull s2 = add2(sa, sb);
            float lo, hi; unpack2(s2, lo, hi);
            float p = ex2f(lo + hi + rbr[kx]);
            l += p;
            ull pp = bcast2(p);
            const ulonglong2* vp = (const ulonglong2*)(vs + kk * C_ + h * HEAD_);
            ulonglong2 va = vp[0], vb = vp[1], vc = vp[2], vd = vp[3];
            FFMA2(acc2[0], pp, va.x); FFMA2(acc2[1], pp, va.y);
            FFMA2(acc2[2], pp, vb.x); FFMA2(acc2[3], pp, vb.y);
            FFMA2(acc2[4], pp, vc.x); FFMA2(acc2[5], pp, vc.y);
            FFMA2(acc2[6], pp, vd.x); FFMA2(acc2[7], pp, vd.y);
        }
    }

    const float inv = 1.f / l;
    float* aop = g_ao + (((size_t)b * HW_) + (size_t)(y0 + qy) * W_ + (x0 + qx)) * C_
               + h * HEAD_;
    #pragma unroll
    for (int d4 = 0; d4 < 4; d4++) {
        float l0, h0, l1, h1;
        unpack2(acc2[d4*2+0], l0, h0);
        unpack2(acc2[d4*2+1], l1, h1);
        float4 o4 = make_float4(l0*inv, h0*inv, l1*inv, h1*inv);
        *(float4*)(aop + d4 * 4) = o4;
    }
}

// ---------------------------------------------------------------------------
// Kernel 3: output projection (R1 version, scalar fp32 — known-good 75us).
// y[b][o][n] = sum_c Wp[o,c] * ao[b][n][c] + pb[o]
// ---------------------------------------------------------------------------
__global__ __launch_bounds__(256) void proj_gemm(const float* __restrict__ w,
                                                 const float* __restrict__ pb,
                                                 float* __restrict__ out)
{
    __shared__ float Ws[64][64];   // [o][c]
    __shared__ float As[64][68];   // [n][c] padded

    const int b  = blockIdx.y;
    const int n0 = blockIdx.x * 64;
    const int tid = threadIdx.x;

    #pragma unroll
    for (int t = tid * 4; t < 4096; t += 1024) {
        *(float4*)&Ws[t >> 6][t & 63] = *(const float4*)(w + t);
    }
    const float* abase = g_ao + ((size_t)b * HW_ + n0) * C_;
    #pragma unroll
    for (int t = tid * 4; t < 4096; t += 1024) {
        int n = t >> 6, c = t & 63;
        *(float4*)&As[n][c] = *(const float4*)(abase + (size_t)n * C_ + c);
    }
    __syncthreads();

    const int i = tid >> 4;
    const int j = tid & 15;

    float acc[4][4] = {};
    #pragma unroll 8
    for (int c4 = 0; c4 < 16; c4++) {
        float4 wv[4], av[4];
        #pragma unroll
        for (int m = 0; m < 4; m++)  wv[m] = *(float4*)&Ws[i*4+m][c4*4];
        #pragma unroll
        for (int nn = 0; nn < 4; nn++) av[nn] = *(float4*)&As[j*4+nn][c4*4];
        #pragma unroll
        for (int m = 0; m < 4; m++)
            #pragma unroll
            for (int nn = 0; nn < 4; nn++)
                acc[m][nn] += wv[m].x*av[nn].x + wv[m].y*av[nn].y
                            + wv[m].z*av[nn].z + wv[m].w*av[nn].w;
    }

    #pragma unroll
    for (int m = 0; m < 4; m++) {
        int o = i*4 + m;
        float bias = __ldg(pb + o);
        float4 o4 = make_float4(acc[m][0] + bias, acc[m][1] + bias,
                                acc[m][2] + bias, acc[m][3] + bias);
        *(float4*)(out + ((size_t)b * C_ + o) * HW_ + n0 + j*4) = o4;
    }
}

// ---------------------------------------------------------------------------
extern "C" void kernel_launch(void* const* d_in, const int* in_sizes, int n_in,
                              void* d_out, int out_size)
{
    const float* x      = (const float*)d_in[0];
    const float* qkv_w  = (const float*)d_in[1];
    const float* qkv_b  = (const float*)d_in[2];
    const float* rpb    = (const float*)d_in[3];
    const float* proj_w = (const float*)d_in[4];
    const float* proj_b = (const float*)d_in[5];
    float* out = (float*)d_out;

    cudaFuncSetAttribute(attn_kernel, cudaFuncAttributeMaxDynamicSharedMemorySize,
                         ATTN_SMEM);

    qkv_gemm<<<dim3(HW_/64, 3, B_), 256>>>(x, qkv_w, qkv_b);
    attn_kernel<<<B_ * NW_, 256, ATTN_SMEM>>>(rpb);
    proj_gemm<<<dim3(HW_/64, B_), 256>>>(proj_w, proj_b, out);
}

// round 5
// speedup vs baseline: 1.6898x; 1.2038x over previous
#include <cuda_runtime.h>
#include <cstddef>

// Problem constants
#define B_    4
#define C_    64
#define H_    256
#define W_    256
#define HW_   (H_*W_)          // 65536
#define WS_   8
#define OWS_  12
#define PAD_  2
#define NO_   144
#define NH_   4
#define HEAD_ 16
#define SCALE_ 0.25f
#define NW_   1024
#define LOG2E_ 1.4426950408889634f

typedef unsigned long long ull;

// ---- packed f32x2 helpers -------------------------------------------------
__device__ __forceinline__ ull bcast2(float v) {
    ull r; asm("mov.b64 %0, {%1,%1};" : "=l"(r) : "f"(v)); return r;
}
__device__ __forceinline__ void unpack2(ull v, float& lo, float& hi) {
    asm("mov.b64 {%0,%1}, %2;" : "=f"(lo), "=f"(hi) : "l"(v));
}
__device__ __forceinline__ ull pack2(float lo, float hi) {
    ull r; asm("mov.b64 %0, {%1,%2};" : "=l"(r) : "f"(lo), "f"(hi)); return r;
}
#define FFMA2(d, a, b) asm("fma.rn.f32x2 %0, %1, %2, %0;" : "+l"(d) : "l"(a), "l"(b))
__device__ __forceinline__ ull mul2(ull a, ull b) {
    ull r; asm("mul.rn.f32x2 %0, %1, %2;" : "=l"(r) : "l"(a), "l"(b)); return r;
}
__device__ __forceinline__ ull add2(ull a, ull b) {
    ull r; asm("add.rn.f32x2 %0, %1, %2;" : "=l"(r) : "l"(a), "l"(b)); return r;
}
__device__ __forceinline__ float ex2f(float x) {
    float r; asm("ex2.approx.f32 %0, %1;" : "=f"(r) : "f"(x)); return r;
}

// Scratch. q/k/v position-major [b][pos][c]; ao CHANNEL-major [b][c][pos].
__device__ float g_q [(size_t)B_*HW_*C_];
__device__ float g_k [(size_t)B_*HW_*C_];
__device__ float g_v [(size_t)B_*HW_*C_];
__device__ float g_ao[(size_t)B_*HW_*C_];

// ---------------------------------------------------------------------------
// Shared GEMM core: out[o,n] = sum_c A[o,c] * Bm[c,n]
// Block tile 64(M) x 128(N) x 64(K), 128 threads, 8x8 micro-tile.
// Wt[c][o] (transposed, pad 68), Xs[c][n]. A-frag = native f32x2 o-pairs.
// Thread (i,j): o = i*8 .. i*8+7 ; n in {j*4..j*4+3} u {64+j*4..64+j*4+3}
// ---------------------------------------------------------------------------
#define GEMM_SMEM ((64*68 + 64*128) * 4)   // 50176 bytes

struct GemmAcc { ull a[4][8]; };  // [o-pair][n-slot]

__device__ __forceinline__ void gemm_core(const float* Wt, const float* Xs,
                                          int i, int j, GemmAcc& G)
{
    const float* wfrag = Wt + i*8;
    const float* xfrag = Xs + j*4;
    #pragma unroll 8
    for (int c = 0; c < 64; c++) {
        ulonglong2 alo = *(const ulonglong2*)(wfrag + c*68);      // o pairs 0,1
        ulonglong2 ahi = *(const ulonglong2*)(wfrag + c*68 + 4);  // o pairs 2,3
        float4 b0 = *(const float4*)(xfrag + c*128);
        float4 b1 = *(const float4*)(xfrag + c*128 + 64);
        ull bb0 = bcast2(b0.x), bb1 = bcast2(b0.y), bb2 = bcast2(b0.z), bb3 = bcast2(b0.w);
        ull bb4 = bcast2(b1.x), bb5 = bcast2(b1.y), bb6 = bcast2(b1.z), bb7 = bcast2(b1.w);
        FFMA2(G.a[0][0], alo.x, bb0); FFMA2(G.a[0][1], alo.x, bb1);
        FFMA2(G.a[0][2], alo.x, bb2); FFMA2(G.a[0][3], alo.x, bb3);
        FFMA2(G.a[0][4], alo.x, bb4); FFMA2(G.a[0][5], alo.x, bb5);
        FFMA2(G.a[0][6], alo.x, bb6); FFMA2(G.a[0][7], alo.x, bb7);
        FFMA2(G.a[1][0], alo.y, bb0); FFMA2(G.a[1][1], alo.y, bb1);
        FFMA2(G.a[1][2], alo.y, bb2); FFMA2(G.a[1][3], alo.y, bb3);
        FFMA2(G.a[1][4], alo.y, bb4); FFMA2(G.a[1][5], alo.y, bb5);
        FFMA2(G.a[1][6], alo.y, bb6); FFMA2(G.a[1][7], alo.y, bb7);
        FFMA2(G.a[2][0], ahi.x, bb0); FFMA2(G.a[2][1], ahi.x, bb1);
        FFMA2(G.a[2][2], ahi.x, bb2); FFMA2(G.a[2][3], ahi.x, bb3);
        FFMA2(G.a[2][4], ahi.x, bb4); FFMA2(G.a[2][5], ahi.x, bb5);
        FFMA2(G.a[2][6], ahi.x, bb6); FFMA2(G.a[2][7], ahi.x, bb7);
        FFMA2(G.a[3][0], ahi.y, bb0); FFMA2(G.a[3][1], ahi.y, bb1);
        FFMA2(G.a[3][2], ahi.y, bb2); FFMA2(G.a[3][3], ahi.y, bb3);
        FFMA2(G.a[3][4], ahi.y, bb4); FFMA2(G.a[3][5], ahi.y, bb5);
        FFMA2(G.a[3][6], ahi.y, bb6); FFMA2(G.a[3][7], ahi.y, bb7);
    }
}

__device__ __forceinline__ void load_w_transposed(float* Wt, const float* wsrc, int tid)
{
    // wsrc: [64][64] row-major -> Wt[c][o] (pad 68). Coalesced LDG, 4-way STS.
    for (int t = tid; t < 4096; t += 128) {
        int o = t >> 6, c = t & 63;
        Wt[c * 68 + o] = wsrc[t];
    }
}

// ---------------------------------------------------------------------------
// Kernel 1: QKV GEMM. grid (512 n-tiles, 3 ot, 4 b), 128 threads.
// Writes q/k/v position-major [n][c].
// ---------------------------------------------------------------------------
__global__ __launch_bounds__(128) void qkv_gemm(const float* __restrict__ x,
                                                const float* __restrict__ w,
                                                const float* __restrict__ qb)
{
    extern __shared__ float sm[];
    float* Wt = sm;             // [64][68]
    float* Xs = sm + 64*68;     // [64][128]

    const int b  = blockIdx.z;
    const int ot = blockIdx.y;
    const int n0 = blockIdx.x * 128;
    const int tid = threadIdx.x;

    load_w_transposed(Wt, w + (size_t)ot * 4096, tid);
    const float* xbase = x + (size_t)b * C_ * HW_ + n0;
    #pragma unroll
    for (int t = tid * 4; t < 64*128; t += 512) {
        int c = t >> 7, n = t & 127;
        *(float4*)&Xs[c*128 + n] = *(const float4*)(xbase + (size_t)c * HW_ + n);
    }
    __syncthreads();

    const int i = tid >> 4;   // 0..7
    const int j = tid & 15;   // 0..15

    GemmAcc G = {};
    gemm_core(Wt, Xs, i, j, G);

    // bias as o-pairs
    #pragma unroll
    for (int p = 0; p < 4; p++) {
        int o = ot*64 + i*8 + p*2;
        ull bp = pack2(__ldg(qb + o), __ldg(qb + o + 1));
        #pragma unroll
        for (int n = 0; n < 8; n++) G.a[p][n] = add2(G.a[p][n], bp);
    }

    float* dst = (ot == 0 ? g_q : (ot == 1 ? g_k : g_v))
               + ((size_t)b * HW_ + n0) * C_ + i*8;
    union { ull u[2]; float4 f; } cv;
    #pragma unroll
    for (int s = 0; s < 2; s++) {        // n-slot group: j*4  /  64+j*4
        #pragma unroll
        for (int nn = 0; nn < 4; nn++) {
            int n = s*64 + j*4 + nn;
            cv.u[0] = G.a[0][s*4+nn]; cv.u[1] = G.a[1][s*4+nn];
            *(float4*)(dst + (size_t)n * C_) = cv.f;
            cv.u[0] = G.a[2][s*4+nn]; cv.u[1] = G.a[3][s*4+nn];
            *(float4*)(dst + (size_t)n * C_ + 4) = cv.f;
        }
    }
}

// ---------------------------------------------------------------------------
// Kernel 2: windowed overlap cross-attention (unchanged math).
// Output now CHANNEL-major g_ao[b][c][n].
// ---------------------------------------------------------------------------
#define ATTN_SMEM ((NO_*C_*2 + NH_*361) * 4)

__global__ __launch_bounds__(256) void attn_kernel(const float* __restrict__ rpb)
{
    extern __shared__ float sm[];
    float* ks = sm;                    // [144][64]
    float* vs = sm + NO_*C_;           // [144][64]
    float* rs = sm + NO_*C_*2;         // [4][361] bias * log2e

    const int tid = threadIdx.x;
    const int b   = blockIdx.x >> 10;
    const int wi  = blockIdx.x & 1023;
    const int wh  = wi >> 5, ww = wi & 31;
    const int y0  = wh * WS_, x0 = ww * WS_;

    const float* kg = g_k + (size_t)b * HW_ * C_;
    const float* vg = g_v + (size_t)b * HW_ * C_;
    for (int t = tid; t < NO_ * (C_/4); t += 256) {
        int kk = t >> 4;
        int c4 = (t & 15) << 2;
        int gy = y0 + kk / OWS_ - PAD_;
        int gx = x0 + kk % OWS_ - PAD_;
        float4 kv = make_float4(0.f, 0.f, 0.f, 0.f);
        float4 vv = make_float4(0.f, 0.f, 0.f, 0.f);
        if ((unsigned)gy < H_ && (unsigned)gx < W_) {
            size_t off = ((size_t)gy * W_ + gx) * C_ + c4;
            kv = *(const float4*)(kg + off);
            vv = *(const float4*)(vg + off);
        }
        *(float4*)&ks[kk * C_ + c4] = kv;
        *(float4*)&vs[kk * C_ + c4] = vv;
    }
    for (int t = tid; t < 361 * NH_; t += 256) {
        int idx = t >> 2, h = t & 3;
        rs[h * 361 + idx] = __ldg(rpb + t) * LOG2E_;
    }

    const int h  = tid >> 6;
    const int qi = tid & 63;
    const int qy = qi >> 3, qx = qi & 7;
    const size_t npos = (size_t)(y0 + qy) * W_ + (x0 + qx);

    const float* qg = g_q + ((size_t)b * HW_ + npos) * C_ + h * HEAD_;
    ull q2[8];
    const float qs = SCALE_ * LOG2E_;
    #pragma unroll
    for (int d4 = 0; d4 < 4; d4++) {
        float4 t4 = *(const float4*)(qg + d4 * 4);
        q2[d4*2+0] = pack2(t4.x * qs, t4.y * qs);
        q2[d4*2+1] = pack2(t4.z * qs, t4.w * qs);
    }
    __syncthreads();

    const float* rb = rs + h * 361 + (7 - qy) * 19 + (7 - qx);

    float l = 0.f;
    ull acc2[8] = {};

    for (int ky = 0; ky < OWS_; ky++) {
        const float* rbr = rb + ky * 19;
        #pragma unroll 6
        for (int kx = 0; kx < OWS_; kx++) {
            const int kk = ky * OWS_ + kx;
            const ulonglong2* kp = (const ulonglong2*)(ks + kk * C_ + h * HEAD_);
            ulonglong2 ka = kp[0], kb = kp[1], kc = kp[2], kd = kp[3];
            ull sa = mul2(q2[0], ka.x);
            ull sb = mul2(q2[1], ka.y);
            FFMA2(sa, q2[2], kb.x); FFMA2(sb, q2[3], kb.y);
            FFMA2(sa, q2[4], kc.x); FFMA2(sb, q2[5], kc.y);
            FFMA2(sa, q2[6], kd.x); FFMA2(sb, q2[7], kd.y);
            ull s2 = add2(sa, sb);
            float lo, hi; unpack2(s2, lo, hi);
            float p = ex2f(lo + hi + rbr[kx]);
            l += p;
            ull pp = bcast2(p);
            const ulonglong2* vp = (const ulonglong2*)(vs + kk * C_ + h * HEAD_);
            ulonglong2 va = vp[0], vb = vp[1], vc = vp[2], vd = vp[3];
            FFMA2(acc2[0], pp, va.x); FFMA2(acc2[1], pp, va.y);
            FFMA2(acc2[2], pp, vb.x); FFMA2(acc2[3], pp, vb.y);
            FFMA2(acc2[4], pp, vc.x); FFMA2(acc2[5], pp, vc.y);
            FFMA2(acc2[6], pp, vd.x); FFMA2(acc2[7], pp, vd.y);
        }
    }

    const float inv = 1.f / l;
    // channel-major store: g_ao[b][c][n], c = h*16 + d
    float* aop = g_ao + ((size_t)b * C_ + h * HEAD_) * HW_ + npos;
    #pragma unroll
    for (int d2 = 0; d2 < 8; d2++) {
        float lo, hi; unpack2(acc2[d2], lo, hi);
        aop[(size_t)(2*d2+0) * HW_] = lo * inv;
        aop[(size_t)(2*d2+1) * HW_] = hi * inv;
    }
}

// ---------------------------------------------------------------------------
// Kernel 3: projection GEMM — same core as qkv. ao is channel-major, so the
// B-tile load is a straight coalesced copy. Output channel-major (natural).
// grid (512 n-tiles, 4 b), 128 threads.
// ---------------------------------------------------------------------------
__global__ __launch_bounds__(128) void proj_gemm(const float* __restrict__ w,
                                                 const float* __restrict__ pb,
                                                 float* __restrict__ out)
{
    extern __shared__ float sm[];
    float* Wt = sm;             // [64][68]
    float* Xs = sm + 64*68;     // [64][128]

    const int b  = blockIdx.y;
    const int n0 = blockIdx.x * 128;
    const int tid = threadIdx.x;

    load_w_transposed(Wt, w, tid);
    const float* abase = g_ao + (size_t)b * C_ * HW_ + n0;
    #pragma unroll
    for (int t = tid * 4; t < 64*128; t += 512) {
        int c = t >> 7, n = t & 127;
        *(float4*)&Xs[c*128 + n] = *(const float4*)(abase + (size_t)c * HW_ + n);
    }
    __syncthreads();

    const int i = tid >> 4;
    const int j = tid & 15;

    GemmAcc G = {};
    gemm_core(Wt, Xs, i, j, G);

    // unpack to o-major and store channel-major rows
    float* dst = out + ((size_t)b * C_ + i*8) * HW_ + n0;
    #pragma unroll
    for (int p = 0; p < 4; p++) {
        float blo = __ldg(pb + i*8 + p*2), bhi = __ldg(pb + i*8 + p*2 + 1);
        float vlo[8], vhi[8];
        #pragma unroll
        for (int n = 0; n < 8; n++) {
            unpack2(G.a[p][n], vlo[n], vhi[n]);
            vlo[n] += blo; vhi[n] += bhi;
        }
        float* r0 = dst + (size_t)(p*2+0) * HW_;
        float* r1 = dst + (size_t)(p*2+1) * HW_;
        *(float4*)(r0 + j*4)      = make_float4(vlo[0], vlo[1], vlo[2], vlo[3]);
        *(float4*)(r0 + 64 + j*4) = make_float4(vlo[4], vlo[5], vlo[6], vlo[7]);
        *(float4*)(r1 + j*4)      = make_float4(vhi[0], vhi[1], vhi[2], vhi[3]);
        *(float4*)(r1 + 64 + j*4) = make_float4(vhi[4], vhi[5], vhi[6], vhi[7]);
    }
}

// ---------------------------------------------------------------------------
extern "C" void kernel_launch(void* const* d_in, const int* in_sizes, int n_in,
                              void* d_out, int out_size)
{
    const float* x      = (const float*)d_in[0];
    const float* qkv_w  = (const float*)d_in[1];
    const float* qkv_b  = (const float*)d_in[2];
    const float* rpb    = (const float*)d_in[3];
    const float* proj_w = (const float*)d_in[4];
    const float* proj_b = (const float*)d_in[5];
    float* out = (float*)d_out;

    cudaFuncSetAttribute(qkv_gemm,  cudaFuncAttributeMaxDynamicSharedMemorySize, GEMM_SMEM);
    cudaFuncSetAttribute(proj_gemm, cudaFuncAttributeMaxDynamicSharedMemorySize, GEMM_SMEM);
    cudaFuncSetAttribute(attn_kernel, cudaFuncAttributeMaxDynamicSharedMemorySize, ATTN_SMEM);

    qkv_gemm<<<dim3(HW_/128, 3, B_), 128, GEMM_SMEM>>>(x, qkv_w, qkv_b);
    attn_kernel<<<B_ * NW_, 256, ATTN_SMEM>>>(rpb);
    proj_gemm<<<dim3(HW_/128, B_), 128, GEMM_SMEM>>>(proj_w, proj_b, out);
}

// round 8
// speedup vs baseline: 1.9489x; 1.1533x over previous
#include <cuda_runtime.h>
#include <cstdint>
#include <cstddef>

// Problem constants
#define B_    4
#define C_    64
#define H_    256
#define W_    256
#define HW_   (H_*W_)          // 65536
#define WS_   8
#define OWS_  12
#define PAD_  2
#define NO_   144
#define NH_   4
#define HEAD_ 16
#define SCALE_ 0.25f
#define NW_   1024
#define LOG2E_ 1.4426950408889634f

typedef unsigned long long ull;

// ---- packed f32x2 helpers (attn) ------------------------------------------
__device__ __forceinline__ ull bcast2(float v) {
    ull r; asm("mov.b64 %0, {%1,%1};" : "=l"(r) : "f"(v)); return r;
}
__device__ __forceinline__ void unpack2(ull v, float& lo, float& hi) {
    asm("mov.b64 {%0,%1}, %2;" : "=f"(lo), "=f"(hi) : "l"(v));
}
__device__ __forceinline__ ull pack2(float lo, float hi) {
    ull r; asm("mov.b64 %0, {%1,%2};" : "=l"(r) : "f"(lo), "f"(hi)); return r;
}
#define FFMA2(d, a, b) asm("fma.rn.f32x2 %0, %1, %2, %0;" : "+l"(d) : "l"(a), "l"(b))
__device__ __forceinline__ ull mul2(ull a, ull b) {
    ull r; asm("mul.rn.f32x2 %0, %1, %2;" : "=l"(r) : "l"(a), "l"(b)); return r;
}
__device__ __forceinline__ ull add2(ull a, ull b) {
    ull r; asm("add.rn.f32x2 %0, %1, %2;" : "=l"(r) : "l"(a), "l"(b)); return r;
}
__device__ __forceinline__ float ex2f(float x) {
    float r; asm("ex2.approx.f32 %0, %1;" : "=f"(r) : "f"(x)); return r;
}

// ---- tf32 helpers ----------------------------------------------------------
__device__ __forceinline__ uint32_t tf32u(float a) {   // rna round to tf32 bits
    uint32_t u; asm("cvt.rna.tf32.f32 %0, %1;" : "=r"(u) : "f"(a));
    return u;
}

// m16n8k8 tf32 mma (sm_80+ PTX; compiles for sm_100)
__device__ __forceinline__ void mma_tf32(float* d,
                                         uint32_t a0, uint32_t a1,
                                         uint32_t a2, uint32_t a3,
                                         uint32_t b0, uint32_t b1)
{
    asm volatile(
        "mma.sync.aligned.m16n8k8.row.col.f32.tf32.tf32.f32 "
        "{%0,%1,%2,%3}, {%4,%5,%6,%7}, {%8,%9}, {%0,%1,%2,%3};"
        : "+f"(d[0]), "+f"(d[1]), "+f"(d[2]), "+f"(d[3])
        : "r"(a0), "r"(a1), "r"(a2), "r"(a3), "r"(b0), "r"(b1));
}

// Scratch. q/k/v position-major [b][pos][c]; ao CHANNEL-major [b][c][pos].
__device__ float g_q [(size_t)B_*HW_*C_];
__device__ float g_k [(size_t)B_*HW_*C_];
__device__ float g_v [(size_t)B_*HW_*C_];
__device__ float g_ao[(size_t)B_*HW_*C_];

// ---------------------------------------------------------------------------
// GEMM via mma.sync tf32.  D[o,n] = sum_c A[o,c] * Bm[c,n]  (+bias)
// Block 64(M) x 128(N) x 64(K), 256 thr, warps 4(M) x 2(N).
// Smem: Ahi[64][68], Alo[64][68] (weight tf32 hi/lo), Xs[64][136] (data tf32).
//   A-frag banks: (68*r + c)%32 = (4r+c), r=lane/4, c=lane%4 -> all distinct.
//   B-frag banks: (136*k + n)%32 = (8k+n), k=lane%4, n=lane/4 -> all distinct.
// ---------------------------------------------------------------------------
#define AHI_OFF  0
#define ALO_OFF  (64*68)
#define XS_OFF   (2*64*68)
#define GEMM_SMEM ((2*64*68 + 64*136) * 4)   // 69632 bytes

struct MmaOut { float d[8][4]; };  // [ntile][reg]

__device__ __forceinline__ void gemm_mma_core(const uint32_t* sm,  // smem as u32
                                              int wid, int lane, MmaOut& O)
{
    const int m0  = (wid & 3) * 16;
    const int nw0 = (wid >> 2) * 64;
    const int lq  = lane >> 2;   // 0..7
    const int lr  = lane & 3;    // 0..3

    // base offsets (in words)
    int aoff = AHI_OFF + (m0 + lq) * 68 + lr;
    int boff = XS_OFF + lr * 136 + nw0 + lq;

    #pragma unroll
    for (int s = 0; s < 8; s++) {
        uint32_t ah0 = sm[aoff],            ah1 = sm[aoff + 8*68];
        uint32_t ah2 = sm[aoff + 4],        ah3 = sm[aoff + 8*68 + 4];
        uint32_t al0 = sm[aoff + ALO_OFF],  al1 = sm[aoff + ALO_OFF + 8*68];
        uint32_t al2 = sm[aoff + ALO_OFF+4],al3 = sm[aoff + ALO_OFF + 8*68 + 4];
        #pragma unroll
        for (int nt = 0; nt < 8; nt++) {
            uint32_t b0 = sm[boff + nt*8];
            uint32_t b1 = sm[boff + nt*8 + 4*136];
            mma_tf32(O.d[nt], ah0, ah1, ah2, ah3, b0, b1);
            mma_tf32(O.d[nt], al0, al1, al2, al3, b0, b1);
        }
        aoff += 8;
        boff += 8*136;
    }
}

// cooperative smem fill: weights (hi/lo split) + data tile (rna tf32)
__device__ __forceinline__ void gemm_fill(uint32_t* sm,
                                          const float* __restrict__ wsrc,
                                          const float* __restrict__ dsrc, // [c][HW] col n0
                                          int tid)
{
    #pragma unroll
    for (int t = tid * 4; t < 4096; t += 1024) {
        int o = t >> 6, c = t & 63;
        float4 v = *(const float4*)(wsrc + o * 64 + c);
        uint32_t h0 = tf32u(v.x), h1 = tf32u(v.y), h2 = tf32u(v.z), h3 = tf32u(v.w);
        uint32_t* ah = sm + AHI_OFF + o * 68 + c;
        uint32_t* al = sm + ALO_OFF + o * 68 + c;
        ah[0] = h0; ah[1] = h1; ah[2] = h2; ah[3] = h3;
        al[0] = tf32u(v.x - __uint_as_float(h0));
        al[1] = tf32u(v.y - __uint_as_float(h1));
        al[2] = tf32u(v.z - __uint_as_float(h2));
        al[3] = tf32u(v.w - __uint_as_float(h3));
    }
    #pragma unroll
    for (int t = tid * 4; t < 8192; t += 1024) {
        int c = t >> 7, n = t & 127;
        float4 v = *(const float4*)(dsrc + (size_t)c * HW_ + n);
        uint32_t* xs = sm + XS_OFF + c * 136 + n;
        xs[0] = tf32u(v.x); xs[1] = tf32u(v.y);
        xs[2] = tf32u(v.z); xs[3] = tf32u(v.w);
    }
}

// ---------------------------------------------------------------------------
// Kernel 1: QKV GEMM. grid (512, 3, 4). Writes q/k/v position-major [n][c].
// ---------------------------------------------------------------------------
__global__ __launch_bounds__(256) void qkv_mma(const float* __restrict__ x,
                                               const float* __restrict__ w,
                                               const float* __restrict__ qb)
{
    extern __shared__ uint32_t smu[];
    const int tid = threadIdx.x;
    const int wid = tid >> 5, lane = tid & 31;
    const int b = blockIdx.z, ot = blockIdx.y, n0 = blockIdx.x * 128;

    gemm_fill(smu, w + (size_t)ot * 4096, x + (size_t)b * C_ * HW_ + n0, tid);
    __syncthreads();

    MmaOut O = {};
    gemm_mma_core(smu, wid, lane, O);

    const int m0  = (wid & 3) * 16;
    const int nw0 = (wid >> 2) * 64;
    const int lq  = lane >> 2, lr = lane & 3;
    const int o0  = m0 + lq;
    const float bias0 = __ldg(qb + ot*64 + o0);
    const float bias1 = __ldg(qb + ot*64 + o0 + 8);

    float* dst = (ot == 0 ? g_q : (ot == 1 ? g_k : g_v))
               + ((size_t)b * HW_ + n0 + nw0) * C_;
    #pragma unroll
    for (int nt = 0; nt < 8; nt++) {
        int nb = nt*8 + lr*2;
        float* p0 = dst + (size_t)nb * C_;
        p0[o0]            = O.d[nt][0] + bias0;
        p0[C_ + o0]       = O.d[nt][1] + bias0;
        p0[o0 + 8]        = O.d[nt][2] + bias1;
        p0[C_ + o0 + 8]   = O.d[nt][3] + bias1;
    }
}

// ---------------------------------------------------------------------------
// Kernel 2: windowed overlap cross-attention (R5, unchanged).
// ---------------------------------------------------------------------------
#define ATTN_SMEM ((NO_*C_*2 + NH_*361) * 4)

__global__ __launch_bounds__(256) void attn_kernel(const float* __restrict__ rpb)
{
    extern __shared__ float sm[];
    float* ks = sm;                    // [144][64]
    float* vs = sm + NO_*C_;           // [144][64]
    float* rs = sm + NO_*C_*2;         // [4][361] bias * log2e

    const int tid = threadIdx.x;
    const int b   = blockIdx.x >> 10;
    const int wi  = blockIdx.x & 1023;
    const int wh  = wi >> 5, ww = wi & 31;
    const int y0  = wh * WS_, x0 = ww * WS_;

    const float* kg = g_k + (size_t)b * HW_ * C_;
    const float* vg = g_v + (size_t)b * HW_ * C_;
    for (int t = tid; t < NO_ * (C_/4); t += 256) {
        int kk = t >> 4;
        int c4 = (t & 15) << 2;
        int gy = y0 + kk / OWS_ - PAD_;
        int gx = x0 + kk % OWS_ - PAD_;
        float4 kv = make_float4(0.f, 0.f, 0.f, 0.f);
        float4 vv = make_float4(0.f, 0.f, 0.f, 0.f);
        if ((unsigned)gy < H_ && (unsigned)gx < W_) {
            size_t off = ((size_t)gy * W_ + gx) * C_ + c4;
            kv = *(const float4*)(kg + off);
            vv = *(const float4*)(vg + off);
        }
        *(float4*)&ks[kk * C_ + c4] = kv;
        *(float4*)&vs[kk * C_ + c4] = vv;
    }
    for (int t = tid; t < 361 * NH_; t += 256) {
        int idx = t >> 2, h = t & 3;
        rs[h * 361 + idx] = __ldg(rpb + t) * LOG2E_;
    }

    const int h  = tid >> 6;
    const int qi = tid & 63;
    const int qy = qi >> 3, qx = qi & 7;
    const size_t npos = (size_t)(y0 + qy) * W_ + (x0 + qx);

    const float* qg = g_q + ((size_t)b * HW_ + npos) * C_ + h * HEAD_;
    ull q2[8];
    const float qs = SCALE_ * LOG2E_;
    #pragma unroll
    for (int d4 = 0; d4 < 4; d4++) {
        float4 t4 = *(const float4*)(qg + d4 * 4);
        q2[d4*2+0] = pack2(t4.x * qs, t4.y * qs);
        q2[d4*2+1] = pack2(t4.z * qs, t4.w * qs);
    }
    __syncthreads();

    const float* rb = rs + h * 361 + (7 - qy) * 19 + (7 - qx);

    float l = 0.f;
    ull acc2[8] = {};

    for (int ky = 0; ky < OWS_; ky++) {
        const float* rbr = rb + ky * 19;
        #pragma unroll 6
        for (int kx = 0; kx < OWS_; kx++) {
            const int kk = ky * OWS_ + kx;
            const ulonglong2* kp = (const ulonglong2*)(ks + kk * C_ + h * HEAD_);
            ulonglong2 ka = kp[0], kb = kp[1], kc = kp[2], kd = kp[3];
            ull sa = mul2(q2[0], ka.x);
            ull sb = mul2(q2[1], ka.y);
            FFMA2(sa, q2[2], kb.x); FFMA2(sb, q2[3], kb.y);
            FFMA2(sa, q2[4], kc.x); FFMA2(sb, q2[5], kc.y);
            FFMA2(sa, q2[6], kd.x); FFMA2(sb, q2[7], kd.y);
            ull s2 = add2(sa, sb);
            float lo, hi; unpack2(s2, lo, hi);
            float p = ex2f(lo + hi + rbr[kx]);
            l += p;
            ull pp = bcast2(p);
            const ulonglong2* vp = (const ulonglong2*)(vs + kk * C_ + h * HEAD_);
            ulonglong2 va = vp[0], vb = vp[1], vc = vp[2], vd = vp[3];
            FFMA2(acc2[0], pp, va.x); FFMA2(acc2[1], pp, va.y);
            FFMA2(acc2[2], pp, vb.x); FFMA2(acc2[3], pp, vb.y);
            FFMA2(acc2[4], pp, vc.x); FFMA2(acc2[5], pp, vc.y);
            FFMA2(acc2[6], pp, vd.x); FFMA2(acc2[7], pp, vd.y);
        }
    }

    const float inv = 1.f / l;
    float* aop = g_ao + ((size_t)b * C_ + h * HEAD_) * HW_ + npos;
    #pragma unroll
    for (int d2 = 0; d2 < 8; d2++) {
        float lo, hi; unpack2(acc2[d2], lo, hi);
        aop[(size_t)(2*d2+0) * HW_] = lo * inv;
        aop[(size_t)(2*d2+1) * HW_] = hi * inv;
    }
}

// ---------------------------------------------------------------------------
// Kernel 3: projection GEMM via mma.sync. B = g_ao channel-major.
// Output channel-major [o][n] -> direct sector-complete stores.
// grid (512, 4).
// ---------------------------------------------------------------------------
__global__ __launch_bounds__(256) void proj_mma(const float* __restrict__ w,
                                                const float* __restrict__ pb,
                                                float* __restrict__ out)
{
    extern __shared__ uint32_t smu[];
    const int tid = threadIdx.x;
    const int wid = tid >> 5, lane = tid & 31;
    const int b = blockIdx.y, n0 = blockIdx.x * 128;

    gemm_fill(smu, w, g_ao + (size_t)b * C_ * HW_ + n0, tid);
    __syncthreads();

    MmaOut O = {};
    gemm_mma_core(smu, wid, lane, O);

    const int m0  = (wid & 3) * 16;
    const int nw0 = (wid >> 2) * 64;
    const int lq  = lane >> 2, lr = lane & 3;
    const int o0  = m0 + lq;
    const float bias0 = __ldg(pb + o0);
    const float bias1 = __ldg(pb + o0 + 8);

    float* r0 = out + ((size_t)b * C_ + o0) * HW_ + n0 + nw0;
    float* r1 = out + ((size_t)b * C_ + o0 + 8) * HW_ + n0 + nw0;
    #pragma unroll
    for (int nt = 0; nt < 8; nt++) {
        int nb = nt*8 + lr*2;
        *(float2*)(r0 + nb) = make_float2(O.d[nt][0] + bias0, O.d[nt][1] + bias0);
        *(float2*)(r1 + nb) = make_float2(O.d[nt][2] + bias1, O.d[nt][3] + bias1);
    }
}

// ---------------------------------------------------------------------------
extern "C" void kernel_launch(void* const* d_in, const int* in_sizes, int n_in,
                              void* d_out, int out_size)
{
    const float* x      = (const float*)d_in[0];
    const float* qkv_w  = (const float*)d_in[1];
    const float* qkv_b  = (const float*)d_in[2];
    const float* rpb    = (const float*)d_in[3];
    const float* proj_w = (const float*)d_in[4];
    const float* proj_b = (const float*)d_in[5];
    float* out = (float*)d_out;

    cudaFuncSetAttribute(qkv_mma,  cudaFuncAttributeMaxDynamicSharedMemorySize, GEMM_SMEM);
    cudaFuncSetAttribute(proj_mma, cudaFuncAttributeMaxDynamicSharedMemorySize, GEMM_SMEM);
    cudaFuncSetAttribute(attn_kernel, cudaFuncAttributeMaxDynamicSharedMemorySize, ATTN_SMEM);

    qkv_mma<<<dim3(HW_/128, 3, B_), 256, GEMM_SMEM>>>(x, qkv_w, qkv_b);
    attn_kernel<<<B_ * NW_, 256, ATTN_SMEM>>>(rpb);
    proj_mma<<<dim3(HW_/128, B_), 256, GEMM_SMEM>>>(proj_w, proj_b, out);
}